// round 4
// baseline (speedup 1.0000x reference)
#include <cuda_runtime.h>
#include <math.h>

#define N_NODES  100000
#define N_EDGES  1600000
#define N_GRAPHS 256
#define F_IN     12
#define HID      64
#define FC_DIM   140
#define POOL_CHUNKS 8

// ---------------- scratch (device globals; no allocation in kernel_launch) ----
__device__ float d_dinv[N_NODES];
__device__ int   d_deg[N_NODES];
__device__ int2  d_edges[N_EDGES];
__device__ __align__(16) float d_g[(size_t)N_NODES * HID];
__device__ __align__(16) float d_acc[(size_t)N_NODES * HID];
__device__ __align__(16) float d_h1[(size_t)N_NODES * HID];
__device__ __align__(16) float d_h2[(size_t)N_NODES * HID];
__device__ float d_pooled[N_GRAPHS * FC_DIM];
__device__ int   d_starts[N_GRAPHS + 1];
__device__ int   d_is32;   // 1 if index inputs are int32, 0 if int64

// ---------------- init + dtype probe ----------------------------------------
__global__ void k_init() {
    int i = blockIdx.x * blockDim.x + threadIdx.x;
    if (i == 0) d_is32 = 0;
    if (i < N_NODES) d_deg[i] = 1;                 // self-loop
    if (i < N_GRAPHS * FC_DIM) d_pooled[i] = 0.0f;
}

// Safe under both dtypes: reads only the int32-sized footprint. If data were
// little-endian int64 (values < 2^31), every odd 32-bit word is 0.
__global__ void k_detect(const int* __restrict__ ei32) {
    int i = blockIdx.x * blockDim.x + threadIdx.x;
    if (i >= N_EDGES) return;
    if (ei32[2 * i + 1] != 0) d_is32 = 1;
}

__global__ void k_count(const void* __restrict__ ei) {
    int e = blockIdx.x * blockDim.x + threadIdx.x;
    if (e >= N_EDGES) return;
    int s, d;
    if (d_is32) {
        const int* p = (const int*)ei;
        s = p[e]; d = p[N_EDGES + e];
    } else {
        const long long* p = (const long long*)ei;
        s = (int)p[e]; d = (int)p[(size_t)N_EDGES + e];
    }
    d_edges[e] = make_int2(s, d);
    atomicAdd(&d_deg[d], 1);
}

__global__ void k_dinv() {
    int i = blockIdx.x * blockDim.x + threadIdx.x;
    if (i < N_NODES) d_dinv[i] = rsqrtf((float)d_deg[i]);
}

// ---------------- layer-1 GEMM: g = dinv * (x @ W1); acc = g (self loop) ----
__global__ void k_gemm1(const float* __restrict__ x, const float* __restrict__ W1) {
    __shared__ float Ws[F_IN * HID];
    __shared__ float xs[4][F_IN];
    int tid = threadIdx.x;                          // 256 threads, 4 rows/block
    for (int i = tid; i < F_IN * HID; i += 256) Ws[i] = W1[i];
    int lr  = tid >> 6;
    int col = tid & 63;
    int r   = blockIdx.x * 4 + lr;                  // N divisible by 4
    if (col < F_IN) xs[lr][col] = x[(size_t)r * F_IN + col];
    __syncthreads();
    float a = 0.0f;
#pragma unroll
    for (int k = 0; k < F_IN; k++) a = fmaf(xs[lr][k], Ws[k * HID + col], a);
    a *= d_dinv[r];
    d_g[(size_t)r * HID + col]   = a;
    d_acc[(size_t)r * HID + col] = a;
}

// ---------------- edge aggregation: acc[dst] += g[src], vectorized red ------
__global__ void k_edge() {
    int t = blockIdx.x * blockDim.x + threadIdx.x;  // 16 threads per edge
    int e = t >> 4;
    if (e >= N_EDGES) return;
    int lane4 = (t & 15) << 2;
    int2 ed = d_edges[e];
    const float4 v = *(const float4*)&d_g[(size_t)ed.x * HID + lane4];
    float* p = &d_acc[(size_t)ed.y * HID + lane4];
    asm volatile("red.global.add.v4.f32 [%0], {%1,%2,%3,%4};"
                 :: "l"(p), "f"(v.x), "f"(v.y), "f"(v.z), "f"(v.w) : "memory");
}

// ---------------- activation: h = tanh(dinv*acc + b) ------------------------
__global__ void k_act(const float* __restrict__ b, int which) {
    int idx = blockIdx.x * blockDim.x + threadIdx.x;   // over N*16 float4s
    if (idx >= N_NODES * 16) return;
    int node = idx >> 4;
    int c4   = (idx & 15) << 2;
    float di = d_dinv[node];
    float4 v = *(const float4*)&d_acc[(size_t)idx * 4];
    float4 o;
    o.x = tanhf(fmaf(di, v.x, b[c4 + 0]));
    o.y = tanhf(fmaf(di, v.y, b[c4 + 1]));
    o.z = tanhf(fmaf(di, v.z, b[c4 + 2]));
    o.w = tanhf(fmaf(di, v.w, b[c4 + 3]));
    float* dst = which ? d_h2 : d_h1;
    *(float4*)&dst[(size_t)idx * 4] = o;
}

// ---------------- layer-2 GEMM: g = dinv * (h1 @ W2); acc = g ---------------
__global__ void k_gemm2(const float* __restrict__ W2) {
    __shared__ __align__(16) float Ws[HID * HID];
    __shared__ float xs[64][65];                     // +1 pad: conflict-free
    int tid = threadIdx.x;
    int row0 = blockIdx.x * 64;
    for (int i = tid; i < HID * HID; i += 256) Ws[i] = W2[i];
    for (int i = tid; i < 1024; i += 256) {          // 64 rows * 16 float4
        int r = i >> 4, c = (i & 15) << 2;
        int gr = row0 + r;
        float4 v = (gr < N_NODES) ? *(const float4*)&d_h1[(size_t)gr * HID + c]
                                  : make_float4(0.f, 0.f, 0.f, 0.f);
        xs[r][c] = v.x; xs[r][c + 1] = v.y; xs[r][c + 2] = v.z; xs[r][c + 3] = v.w;
    }
    __syncthreads();
    int tx = tid & 15, ty = tid >> 4;
    int c0 = tx << 2;
    float acc[4][4] = {};
#pragma unroll 8
    for (int k = 0; k < HID; k++) {
        float4 w = *(const float4*)&Ws[k * HID + c0];
#pragma unroll
        for (int r = 0; r < 4; r++) {
            float xv = xs[ty * 4 + r][k];
            acc[r][0] = fmaf(xv, w.x, acc[r][0]);
            acc[r][1] = fmaf(xv, w.y, acc[r][1]);
            acc[r][2] = fmaf(xv, w.z, acc[r][2]);
            acc[r][3] = fmaf(xv, w.w, acc[r][3]);
        }
    }
#pragma unroll
    for (int r = 0; r < 4; r++) {
        int gr = row0 + ty * 4 + r;
        if (gr < N_NODES) {
            float di = d_dinv[gr];
            float4 o = make_float4(acc[r][0] * di, acc[r][1] * di,
                                   acc[r][2] * di, acc[r][3] * di);
            *(float4*)&d_g[(size_t)gr * HID + c0]   = o;
            *(float4*)&d_acc[(size_t)gr * HID + c0] = o;
        }
    }
}

// ---------------- graph segment boundaries (batch is sorted) ----------------
__global__ void k_bounds(const void* __restrict__ batch) {
    int g = blockIdx.x * blockDim.x + threadIdx.x;
    if (g > N_GRAPHS) return;
    const int*       b32 = (const int*)batch;
    const long long* b64 = (const long long*)batch;
    int is32 = d_is32;
    int lo = 0, hi = N_NODES;
    while (lo < hi) {
        int mid = (lo + hi) >> 1;
        long long v = is32 ? (long long)b32[mid] : b64[mid];
        if (v < (long long)g) lo = mid + 1; else hi = mid;
    }
    d_starts[g] = lo;
}

// ---------------- pooled[g] += sum over nodes of [x | h1 | h2] --------------
__global__ void k_pool(const float* __restrict__ x) {
    int g = blockIdx.x >> 3;
    int chunk = blockIdx.x & (POOL_CHUNKS - 1);
    int s = d_starts[g], e = d_starts[g + 1];
    int len = e - s;
    int cs = s + (int)(((long long)len * chunk) / POOL_CHUNKS);
    int ce = s + (int)(((long long)len * (chunk + 1)) / POOL_CHUNKS);
    int c = threadIdx.x;                             // 140 threads
    float sum = 0.0f;
    if (c < F_IN) {
        for (int i = cs; i < ce; i++) sum += x[(size_t)i * F_IN + c];
    } else if (c < F_IN + HID) {
        int cc = c - F_IN;
        for (int i = cs; i < ce; i++) sum += d_h1[(size_t)i * HID + cc];
    } else {
        int cc = c - F_IN - HID;
        for (int i = cs; i < ce; i++) sum += d_h2[(size_t)i * HID + cc];
    }
    atomicAdd(&d_pooled[g * FC_DIM + c], sum);
}

// ---------------- final FC: out = pooled @ fc_W^T + fc_b --------------------
__global__ void k_fc(const float* __restrict__ fcW, const float* __restrict__ fcb,
                     float* __restrict__ out) {
    __shared__ float ps[FC_DIM];
    int g = blockIdx.x;
    int o = threadIdx.x;                             // 140 threads
    ps[o] = d_pooled[g * FC_DIM + o];
    __syncthreads();
    float a = fcb[o];
#pragma unroll 4
    for (int k = 0; k < FC_DIM; k++) a = fmaf(ps[k], fcW[o * FC_DIM + k], a);
    out[g * FC_DIM + o] = a;
}

// ---------------- launch ----------------------------------------------------
extern "C" void kernel_launch(void* const* d_in, const int* in_sizes, int n_in,
                              void* d_out, int out_size) {
    const float* x    = (const float*)d_in[0];
    const float* W1   = (const float*)d_in[1];
    const float* b1   = (const float*)d_in[2];
    const float* W2   = (const float*)d_in[3];
    const float* b2   = (const float*)d_in[4];
    const float* fcW  = (const float*)d_in[5];
    const float* fcb  = (const float*)d_in[6];
    const void*  ei   = d_in[7];
    const void*  batch= d_in[8];
    float*       out  = (float*)d_out;

    k_init  <<<(N_NODES + 255) / 256, 256>>>();
    k_detect<<<(N_EDGES + 255) / 256, 256>>>((const int*)ei);
    k_count <<<(N_EDGES + 255) / 256, 256>>>(ei);
    k_dinv  <<<(N_NODES + 255) / 256, 256>>>();

    // layer 1
    k_gemm1<<<N_NODES / 4, 256>>>(x, W1);
    k_edge <<<(N_EDGES * 16) / 256, 256>>>();
    k_act  <<<(N_NODES * 16 + 255) / 256, 256>>>(b1, 0);

    // layer 2
    k_gemm2<<<(N_NODES + 63) / 64, 256>>>(W2);
    k_edge <<<(N_EDGES * 16) / 256, 256>>>();
    k_act  <<<(N_NODES * 16 + 255) / 256, 256>>>(b2, 1);

    // pooling + FC
    k_bounds<<<1, 512>>>(batch);
    k_pool  <<<N_GRAPHS * POOL_CHUNKS, FC_DIM>>>(x);
    k_fc    <<<N_GRAPHS, FC_DIM>>>(fcW, fcb, out);
}

// round 5
// speedup vs baseline: 1.5654x; 1.5654x over previous
#include <cuda_runtime.h>
#include <math.h>

#define N_NODES  100000
#define N_EDGES  1600000
#define N_GRAPHS 256
#define F_IN     12
#define HID      64
#define FC_DIM   140
#define POOL_CHUNKS 8
#define SCAN_T   1024

// ---------------- scratch (device globals; no allocation in kernel_launch) ----
__device__ float d_dinv[N_NODES];
__device__ int   d_deg[N_NODES];
__device__ int   d_cursor[N_NODES];
__device__ int   d_rowstart[N_NODES + 1];
__device__ int2  d_edges[N_EDGES];
__device__ int   d_csr[N_EDGES];
__device__ __align__(16) float d_g [(size_t)N_NODES * HID];
__device__ __align__(16) float d_h1[(size_t)N_NODES * HID];
__device__ __align__(16) float d_h2[(size_t)N_NODES * HID];
__device__ float d_pooled[N_GRAPHS * FC_DIM];
__device__ int   d_starts[N_GRAPHS + 1];
__device__ int   d_is32;   // 1 if index inputs are int32, 0 if int64

// ---------------- init + dtype probe ----------------------------------------
__global__ void k_init() {
    int i = blockIdx.x * blockDim.x + threadIdx.x;
    if (i == 0) d_is32 = 0;
    if (i < N_NODES) { d_deg[i] = 1; d_cursor[i] = 0; }   // self-loop in deg
    if (i < N_GRAPHS * FC_DIM) d_pooled[i] = 0.0f;
}

// Probe 4096 odd 32-bit words. int64 (values < 2^31, LE): all high words are 0.
// int32: these are random node indices, ~certainly some nonzero.
__global__ void k_detect(const int* __restrict__ ei32) {
    int i = blockIdx.x * blockDim.x + threadIdx.x;   // 4096 threads
    if (ei32[2 * i + 1] != 0) d_is32 = 1;
}

__global__ void k_count(const void* __restrict__ ei) {
    int e = blockIdx.x * blockDim.x + threadIdx.x;
    if (e >= N_EDGES) return;
    int s, d;
    if (d_is32) {
        const int* p = (const int*)ei;
        s = p[e]; d = p[N_EDGES + e];
    } else {
        const long long* p = (const long long*)ei;
        s = (int)p[e]; d = (int)p[(size_t)N_EDGES + e];
    }
    d_edges[e] = make_int2(s, d);
    atomicAdd(&d_deg[d], 1);
}

__global__ void k_dinv() {
    int i = blockIdx.x * blockDim.x + threadIdx.x;
    if (i < N_NODES) d_dinv[i] = rsqrtf((float)d_deg[i]);
}

// ---------------- exclusive scan of (deg-1) -> rowstart (one block) ---------
__global__ void k_scan() {
    __shared__ int partial[SCAN_T];
    const int chunk = (N_NODES + SCAN_T - 1) / SCAN_T;   // 98
    int tid = threadIdx.x;
    int beg = tid * chunk;
    int end = min(beg + chunk, N_NODES);
    int s = 0;
    for (int i = beg; i < end; i++) s += d_deg[i] - 1;
    partial[tid] = s;
    __syncthreads();
    for (int off = 1; off < SCAN_T; off <<= 1) {
        int v = (tid >= off) ? partial[tid - off] : 0;
        __syncthreads();
        if (tid >= off) partial[tid] += v;
        __syncthreads();
    }
    int run = (tid > 0) ? partial[tid - 1] : 0;
    for (int i = beg; i < end; i++) {
        d_rowstart[i] = run;
        run += d_deg[i] - 1;
    }
    if (tid == SCAN_T - 1) d_rowstart[N_NODES] = run;
}

// ---------------- scatter edges into CSR (grouped by dst) -------------------
__global__ void k_scatter() {
    int e = blockIdx.x * blockDim.x + threadIdx.x;
    if (e >= N_EDGES) return;
    int2 ed = d_edges[e];
    int pos = d_rowstart[ed.y] + atomicAdd(&d_cursor[ed.y], 1);
    d_csr[pos] = ed.x;
}

// ---------------- layer-1 GEMM: g = dinv * (x @ W1) -------------------------
__global__ void k_gemm1(const float* __restrict__ x, const float* __restrict__ W1) {
    __shared__ float Ws[F_IN * HID];
    __shared__ float xs[4][F_IN];
    int tid = threadIdx.x;                          // 256 threads, 4 rows/block
    for (int i = tid; i < F_IN * HID; i += 256) Ws[i] = W1[i];
    int lr  = tid >> 6;
    int col = tid & 63;
    int r   = blockIdx.x * 4 + lr;                  // N divisible by 4
    if (col < F_IN) xs[lr][col] = x[(size_t)r * F_IN + col];
    __syncthreads();
    float a = 0.0f;
#pragma unroll
    for (int k = 0; k < F_IN; k++) a = fmaf(xs[lr][k], Ws[k * HID + col], a);
    d_g[(size_t)r * HID + col] = a * d_dinv[r];
}

// ---------------- pull aggregation + fused activation -----------------------
// 16 threads per node; acc seeded with self-loop; h = tanh(dinv*sum + b)
__global__ void k_agg(const float* __restrict__ b, int which) {
    int t = blockIdx.x * blockDim.x + threadIdx.x;
    int node = t >> 4;
    if (node >= N_NODES) return;
    int c0 = (t & 15) << 2;
    float4 a = *(const float4*)&d_g[(size_t)node * HID + c0];   // self loop
    int s0 = d_rowstart[node], s1 = d_rowstart[node + 1];
#pragma unroll 4
    for (int i = s0; i < s1; i++) {
        int s = d_csr[i];
        float4 v = *(const float4*)&d_g[(size_t)s * HID + c0];
        a.x += v.x; a.y += v.y; a.z += v.z; a.w += v.w;
    }
    float di = d_dinv[node];
    float4 o;
    o.x = tanhf(fmaf(di, a.x, b[c0 + 0]));
    o.y = tanhf(fmaf(di, a.y, b[c0 + 1]));
    o.z = tanhf(fmaf(di, a.z, b[c0 + 2]));
    o.w = tanhf(fmaf(di, a.w, b[c0 + 3]));
    float* dst = which ? d_h2 : d_h1;
    *(float4*)&dst[(size_t)node * HID + c0] = o;
}

// ---------------- layer-2 GEMM: g = dinv * (h1 @ W2) ------------------------
__global__ void k_gemm2(const float* __restrict__ W2) {
    __shared__ __align__(16) float Ws[HID * HID];
    __shared__ float xs[64][65];                     // +1 pad: conflict-free
    int tid = threadIdx.x;
    int row0 = blockIdx.x * 64;
    for (int i = tid; i < HID * HID; i += 256) Ws[i] = W2[i];
    for (int i = tid; i < 1024; i += 256) {          // 64 rows * 16 float4
        int r = i >> 4, c = (i & 15) << 2;
        int gr = row0 + r;
        float4 v = (gr < N_NODES) ? *(const float4*)&d_h1[(size_t)gr * HID + c]
                                  : make_float4(0.f, 0.f, 0.f, 0.f);
        xs[r][c] = v.x; xs[r][c + 1] = v.y; xs[r][c + 2] = v.z; xs[r][c + 3] = v.w;
    }
    __syncthreads();
    int tx = tid & 15, ty = tid >> 4;
    int c0 = tx << 2;
    float acc[4][4] = {};
#pragma unroll 8
    for (int k = 0; k < HID; k++) {
        float4 w = *(const float4*)&Ws[k * HID + c0];
#pragma unroll
        for (int r = 0; r < 4; r++) {
            float xv = xs[ty * 4 + r][k];
            acc[r][0] = fmaf(xv, w.x, acc[r][0]);
            acc[r][1] = fmaf(xv, w.y, acc[r][1]);
            acc[r][2] = fmaf(xv, w.z, acc[r][2]);
            acc[r][3] = fmaf(xv, w.w, acc[r][3]);
        }
    }
#pragma unroll
    for (int r = 0; r < 4; r++) {
        int gr = row0 + ty * 4 + r;
        if (gr < N_NODES) {
            float di = d_dinv[gr];
            float4 o = make_float4(acc[r][0] * di, acc[r][1] * di,
                                   acc[r][2] * di, acc[r][3] * di);
            *(float4*)&d_g[(size_t)gr * HID + c0] = o;
        }
    }
}

// ---------------- graph segment boundaries (batch is sorted) ----------------
__global__ void k_bounds(const void* __restrict__ batch) {
    int g = blockIdx.x * blockDim.x + threadIdx.x;
    if (g > N_GRAPHS) return;
    const int*       b32 = (const int*)batch;
    const long long* b64 = (const long long*)batch;
    int is32 = d_is32;
    int lo = 0, hi = N_NODES;
    while (lo < hi) {
        int mid = (lo + hi) >> 1;
        long long v = is32 ? (long long)b32[mid] : b64[mid];
        if (v < (long long)g) lo = mid + 1; else hi = mid;
    }
    d_starts[g] = lo;
}

// ---------------- pooled[g] += sum over nodes of [x | h1 | h2] --------------
__global__ void k_pool(const float* __restrict__ x) {
    int g = blockIdx.x >> 3;
    int chunk = blockIdx.x & (POOL_CHUNKS - 1);
    int s = d_starts[g], e = d_starts[g + 1];
    int len = e - s;
    int cs = s + (int)(((long long)len * chunk) / POOL_CHUNKS);
    int ce = s + (int)(((long long)len * (chunk + 1)) / POOL_CHUNKS);
    int c = threadIdx.x;                             // 140 threads
    float sum = 0.0f;
    if (c < F_IN) {
        for (int i = cs; i < ce; i++) sum += x[(size_t)i * F_IN + c];
    } else if (c < F_IN + HID) {
        int cc = c - F_IN;
        for (int i = cs; i < ce; i++) sum += d_h1[(size_t)i * HID + cc];
    } else {
        int cc = c - F_IN - HID;
        for (int i = cs; i < ce; i++) sum += d_h2[(size_t)i * HID + cc];
    }
    atomicAdd(&d_pooled[g * FC_DIM + c], sum);
}

// ---------------- final FC: out = pooled @ fc_W^T + fc_b --------------------
__global__ void k_fc(const float* __restrict__ fcW, const float* __restrict__ fcb,
                     float* __restrict__ out) {
    __shared__ float ps[FC_DIM];
    int g = blockIdx.x;
    int o = threadIdx.x;                             // 140 threads
    ps[o] = d_pooled[g * FC_DIM + o];
    __syncthreads();
    float a = fcb[o];
#pragma unroll 4
    for (int k = 0; k < FC_DIM; k++) a = fmaf(ps[k], fcW[o * FC_DIM + k], a);
    out[g * FC_DIM + o] = a;
}

// ---------------- launch ----------------------------------------------------
extern "C" void kernel_launch(void* const* d_in, const int* in_sizes, int n_in,
                              void* d_out, int out_size) {
    const float* x    = (const float*)d_in[0];
    const float* W1   = (const float*)d_in[1];
    const float* b1   = (const float*)d_in[2];
    const float* W2   = (const float*)d_in[3];
    const float* b2   = (const float*)d_in[4];
    const float* fcW  = (const float*)d_in[5];
    const float* fcb  = (const float*)d_in[6];
    const void*  ei   = d_in[7];
    const void*  batch= d_in[8];
    float*       out  = (float*)d_out;

    // preprocessing: dtype probe, compact edges, degrees, CSR
    k_init   <<<(N_NODES + 255) / 256, 256>>>();
    k_detect <<<16, 256>>>((const int*)ei);
    k_count  <<<(N_EDGES + 255) / 256, 256>>>(ei);
    k_dinv   <<<(N_NODES + 255) / 256, 256>>>();
    k_scan   <<<1, SCAN_T>>>();
    k_scatter<<<(N_EDGES + 255) / 256, 256>>>();

    // layer 1
    k_gemm1<<<N_NODES / 4, 256>>>(x, W1);
    k_agg  <<<(N_NODES * 16 + 255) / 256, 256>>>(b1, 0);

    // layer 2
    k_gemm2<<<(N_NODES + 63) / 64, 256>>>(W2);
    k_agg  <<<(N_NODES * 16 + 255) / 256, 256>>>(b2, 1);

    // pooling + FC
    k_bounds<<<1, 512>>>(batch);
    k_pool  <<<N_GRAPHS * POOL_CHUNKS, FC_DIM>>>(x);
    k_fc    <<<N_GRAPHS, FC_DIM>>>(fcW, fcb, out);
}

// round 6
// speedup vs baseline: 1.5987x; 1.0213x over previous
#include <cuda_runtime.h>
#include <cuda_fp16.h>
#include <math.h>

#define N_NODES  100000
#define N_EDGES  1600000
#define N_GRAPHS 256
#define F_IN     12
#define HID      64
#define FC_DIM   140
#define POOL_CHUNKS 8
#define SCAN_T   1024

// ---------------- scratch (device globals; no allocation in kernel_launch) ----
__device__ int   d_deg[N_NODES];
__device__ int   d_cursor[N_NODES];
__device__ int   d_rowstart[N_NODES + 1];
__device__ int2  d_edges[N_EDGES];
__device__ int   d_csr[N_EDGES];
__device__ __align__(16) __half d_g[(size_t)N_NODES * HID];   // fp16 message table
__device__ __align__(16) float  d_h1[(size_t)N_NODES * HID];
__device__ __align__(16) float  d_h2[(size_t)N_NODES * HID];
__device__ float d_pooled[N_GRAPHS * FC_DIM];
__device__ int   d_starts[N_GRAPHS + 1];
__device__ int   d_is32;   // 1 if index inputs are int32, 0 if int64

__device__ __forceinline__ float htanh(float x) {
    float r;
    asm("tanh.approx.f32 %0, %1;" : "=f"(r) : "f"(x));
    return r;
}

// ---------------- init + dtype probe ----------------------------------------
__global__ void k_init() {
    int i = blockIdx.x * blockDim.x + threadIdx.x;
    if (i == 0) d_is32 = 0;
    if (i < N_NODES) { d_deg[i] = 1; d_cursor[i] = 0; }   // self-loop in deg
    if (i < N_GRAPHS * FC_DIM) d_pooled[i] = 0.0f;
}

// Probe 4096 odd 32-bit words. int64 (values < 2^31, LE): all high words are 0.
__global__ void k_detect(const int* __restrict__ ei32) {
    int i = blockIdx.x * blockDim.x + threadIdx.x;
    if (ei32[2 * i + 1] != 0) d_is32 = 1;
}

__global__ void k_count(const void* __restrict__ ei) {
    int e = blockIdx.x * blockDim.x + threadIdx.x;
    if (e >= N_EDGES) return;
    int s, d;
    if (d_is32) {
        const int* p = (const int*)ei;
        s = p[e]; d = p[N_EDGES + e];
    } else {
        const long long* p = (const long long*)ei;
        s = (int)p[e]; d = (int)p[(size_t)N_EDGES + e];
    }
    d_edges[e] = make_int2(s, d);
    atomicAdd(&d_deg[d], 1);
}

// ---------------- exclusive scan of (deg-1) -> rowstart (one block) ---------
__global__ void k_scan() {
    __shared__ int partial[SCAN_T];
    const int chunk = (N_NODES + SCAN_T - 1) / SCAN_T;
    int tid = threadIdx.x;
    int beg = tid * chunk;
    int end = min(beg + chunk, N_NODES);
    int s = 0;
    for (int i = beg; i < end; i++) s += d_deg[i] - 1;
    partial[tid] = s;
    __syncthreads();
    for (int off = 1; off < SCAN_T; off <<= 1) {
        int v = (tid >= off) ? partial[tid - off] : 0;
        __syncthreads();
        if (tid >= off) partial[tid] += v;
        __syncthreads();
    }
    int run = (tid > 0) ? partial[tid - 1] : 0;
    for (int i = beg; i < end; i++) {
        d_rowstart[i] = run;
        run += d_deg[i] - 1;
    }
    if (tid == SCAN_T - 1) d_rowstart[N_NODES] = run;
}

// ---------------- scatter edges into CSR (grouped by dst) -------------------
__global__ void k_scatter() {
    int e = blockIdx.x * blockDim.x + threadIdx.x;
    if (e >= N_EDGES) return;
    int2 ed = d_edges[e];
    int pos = d_rowstart[ed.y] + atomicAdd(&d_cursor[ed.y], 1);
    d_csr[pos] = ed.x;
}

// ---------------- layer-1 GEMM: g = dinv * (x @ W1)  (fp16 out) -------------
__global__ void k_gemm1(const float* __restrict__ x, const float* __restrict__ W1) {
    __shared__ float Ws[F_IN * HID];
    __shared__ float xs[4][F_IN];
    int tid = threadIdx.x;                          // 256 threads, 4 rows/block
    for (int i = tid; i < F_IN * HID; i += 256) Ws[i] = W1[i];
    int lr  = tid >> 6;
    int col = tid & 63;
    int r   = blockIdx.x * 4 + lr;                  // N divisible by 4
    if (col < F_IN) xs[lr][col] = x[(size_t)r * F_IN + col];
    __syncthreads();
    float a = 0.0f;
#pragma unroll
    for (int k = 0; k < F_IN; k++) a = fmaf(xs[lr][k], Ws[k * HID + col], a);
    float dinv = rsqrtf((float)d_deg[r]);
    d_g[(size_t)r * HID + col] = __float2half(a * dinv);
}

// ---------------- pull aggregation + fused activation -----------------------
// 16 threads/node, 8B (4 halves) each -> one 128B line per gathered row.
__global__ void k_agg(const float* __restrict__ b, int which) {
    int t = blockIdx.x * blockDim.x + threadIdx.x;
    int node = t >> 4;
    if (node >= N_NODES) return;
    int lane = t & 15;
    int c0 = lane << 2;
    const uint2* gp = (const uint2*)d_g;            // 4 halves per uint2

    uint2 w = gp[(size_t)node * 16 + lane];         // self loop
    __half2 p0 = *(__half2*)&w.x, p1 = *(__half2*)&w.y;
    float2 f0 = __half22float2(p0), f1 = __half22float2(p1);
    float ax = f0.x, ay = f0.y, az = f1.x, aw = f1.y;

    int s0 = d_rowstart[node], s1 = d_rowstart[node + 1];
    for (int i = s0; i < s1; i++) {
        int s = d_csr[i];
        uint2 u = gp[(size_t)s * 16 + lane];
        __half2 q0 = *(__half2*)&u.x, q1 = *(__half2*)&u.y;
        float2 g0 = __half22float2(q0), g1 = __half22float2(q1);
        ax += g0.x; ay += g0.y; az += g1.x; aw += g1.y;
    }
    float di = rsqrtf((float)d_deg[node]);
    float4 o;
    o.x = htanh(fmaf(di, ax, b[c0 + 0]));
    o.y = htanh(fmaf(di, ay, b[c0 + 1]));
    o.z = htanh(fmaf(di, az, b[c0 + 2]));
    o.w = htanh(fmaf(di, aw, b[c0 + 3]));
    float* dst = which ? d_h2 : d_h1;
    *(float4*)&dst[(size_t)node * HID + c0] = o;
}

// ---------------- layer-2 GEMM: g = dinv * (h1 @ W2)  (fp16 out) ------------
__global__ void k_gemm2(const float* __restrict__ W2) {
    __shared__ __align__(16) float Ws[HID * HID];
    __shared__ float xs[64][65];                     // +1 pad: conflict-free
    int tid = threadIdx.x;
    int row0 = blockIdx.x * 64;
    for (int i = tid; i < HID * HID; i += 256) Ws[i] = W2[i];
    for (int i = tid; i < 1024; i += 256) {          // 64 rows * 16 float4
        int r = i >> 4, c = (i & 15) << 2;
        int gr = row0 + r;
        float4 v = (gr < N_NODES) ? *(const float4*)&d_h1[(size_t)gr * HID + c]
                                  : make_float4(0.f, 0.f, 0.f, 0.f);
        xs[r][c] = v.x; xs[r][c + 1] = v.y; xs[r][c + 2] = v.z; xs[r][c + 3] = v.w;
    }
    __syncthreads();
    int tx = tid & 15, ty = tid >> 4;
    int c0 = tx << 2;
    float acc[4][4] = {};
#pragma unroll 8
    for (int k = 0; k < HID; k++) {
        float4 w = *(const float4*)&Ws[k * HID + c0];
#pragma unroll
        for (int r = 0; r < 4; r++) {
            float xv = xs[ty * 4 + r][k];
            acc[r][0] = fmaf(xv, w.x, acc[r][0]);
            acc[r][1] = fmaf(xv, w.y, acc[r][1]);
            acc[r][2] = fmaf(xv, w.z, acc[r][2]);
            acc[r][3] = fmaf(xv, w.w, acc[r][3]);
        }
    }
#pragma unroll
    for (int r = 0; r < 4; r++) {
        int gr = row0 + ty * 4 + r;
        if (gr < N_NODES) {
            float di = rsqrtf((float)d_deg[gr]);
            __half2 h0 = __floats2half2_rn(acc[r][0] * di, acc[r][1] * di);
            __half2 h1 = __floats2half2_rn(acc[r][2] * di, acc[r][3] * di);
            uint2 u;
            u.x = *(unsigned*)&h0; u.y = *(unsigned*)&h1;
            ((uint2*)d_g)[(size_t)gr * 16 + tx] = u;
        }
    }
}

// ---------------- graph segment boundaries (batch is sorted) ----------------
__global__ void k_bounds(const void* __restrict__ batch) {
    int g = blockIdx.x * blockDim.x + threadIdx.x;
    if (g > N_GRAPHS) return;
    const int*       b32 = (const int*)batch;
    const long long* b64 = (const long long*)batch;
    int is32 = d_is32;
    int lo = 0, hi = N_NODES;
    while (lo < hi) {
        int mid = (lo + hi) >> 1;
        long long v = is32 ? (long long)b32[mid] : b64[mid];
        if (v < (long long)g) lo = mid + 1; else hi = mid;
    }
    d_starts[g] = lo;
}

// ---------------- pooled[g] += sum over nodes of [x | h1 | h2] --------------
__global__ void k_pool(const float* __restrict__ x) {
    int g = blockIdx.x >> 3;
    int chunk = blockIdx.x & (POOL_CHUNKS - 1);
    int s = d_starts[g], e = d_starts[g + 1];
    int len = e - s;
    int cs = s + (int)(((long long)len * chunk) / POOL_CHUNKS);
    int ce = s + (int)(((long long)len * (chunk + 1)) / POOL_CHUNKS);
    int c = threadIdx.x;                             // 140 threads
    float sum = 0.0f;
    if (c < F_IN) {
        for (int i = cs; i < ce; i++) sum += x[(size_t)i * F_IN + c];
    } else if (c < F_IN + HID) {
        int cc = c - F_IN;
        for (int i = cs; i < ce; i++) sum += d_h1[(size_t)i * HID + cc];
    } else {
        int cc = c - F_IN - HID;
        for (int i = cs; i < ce; i++) sum += d_h2[(size_t)i * HID + cc];
    }
    atomicAdd(&d_pooled[g * FC_DIM + c], sum);
}

// ---------------- final FC: out = pooled @ fc_W^T + fc_b --------------------
__global__ void k_fc(const float* __restrict__ fcW, const float* __restrict__ fcb,
                     float* __restrict__ out) {
    __shared__ float ps[FC_DIM];
    int g = blockIdx.x;
    int o = threadIdx.x;                             // 140 threads
    ps[o] = d_pooled[g * FC_DIM + o];
    __syncthreads();
    float a = fcb[o];
#pragma unroll 4
    for (int k = 0; k < FC_DIM; k++) a = fmaf(ps[k], fcW[o * FC_DIM + k], a);
    out[g * FC_DIM + o] = a;
}

// ---------------- launch ----------------------------------------------------
extern "C" void kernel_launch(void* const* d_in, const int* in_sizes, int n_in,
                              void* d_out, int out_size) {
    const float* x    = (const float*)d_in[0];
    const float* W1   = (const float*)d_in[1];
    const float* b1   = (const float*)d_in[2];
    const float* W2   = (const float*)d_in[3];
    const float* b2   = (const float*)d_in[4];
    const float* fcW  = (const float*)d_in[5];
    const float* fcb  = (const float*)d_in[6];
    const void*  ei   = d_in[7];
    const void*  batch= d_in[8];
    float*       out  = (float*)d_out;

    // preprocessing: dtype probe, compact edges, degrees, CSR
    k_init   <<<(N_NODES + 255) / 256, 256>>>();
    k_detect <<<16, 256>>>((const int*)ei);
    k_count  <<<(N_EDGES + 255) / 256, 256>>>(ei);
    k_scan   <<<1, SCAN_T>>>();
    k_scatter<<<(N_EDGES + 255) / 256, 256>>>();

    // layer 1
    k_gemm1<<<N_NODES / 4, 256>>>(x, W1);
    k_agg  <<<(N_NODES * 16 + 255) / 256, 256>>>(b1, 0);

    // layer 2
    k_gemm2<<<(N_NODES + 63) / 64, 256>>>(W2);
    k_agg  <<<(N_NODES * 16 + 255) / 256, 256>>>(b2, 1);

    // pooling + FC
    k_bounds<<<1, 512>>>(batch);
    k_pool  <<<N_GRAPHS * POOL_CHUNKS, FC_DIM>>>(x);
    k_fc    <<<N_GRAPHS, FC_DIM>>>(fcW, fcb, out);
}

// round 8
// speedup vs baseline: 2.4061x; 1.5050x over previous
#include <cuda_runtime.h>
#include <cuda_fp16.h>
#include <math.h>

#define N_NODES  100000
#define N_EDGES  1600000
#define N_GRAPHS 256
#define F_IN     12
#define HID      64
#define FC_DIM   140
#define POOL_CHUNKS 8
#define NBLK     391          // ceil(N_NODES/256)

// ---------------- scratch (device globals; no allocation in kernel_launch) ----
__device__ int   d_deg[N_NODES];
__device__ int   d_cursor[N_NODES];
__device__ int   d_rowstart[N_NODES + 1];
__device__ int   d_bsum[NBLK];
__device__ int   d_boff[NBLK];
__device__ int2  d_edges[N_EDGES];
__device__ int   d_csr[N_EDGES];
__device__ __align__(16) __half d_g[(size_t)N_NODES * HID];   // fp16 message table
__device__ __align__(16) float  d_h1[(size_t)N_NODES * HID];
__device__ __align__(16) float  d_h2[(size_t)N_NODES * HID];
__device__ float d_pooled[N_GRAPHS * FC_DIM];
__device__ int   d_starts[N_GRAPHS + 1];
__device__ int   d_is32;   // 1 if index inputs are int32, 0 if int64

__device__ __forceinline__ float htanh(float x) {
    float r;
    asm("tanh.approx.f32 %0, %1;" : "=f"(r) : "f"(x));
    return r;
}

// ---------------- init + dtype probe ----------------------------------------
__global__ void k_init() {
    int i = blockIdx.x * blockDim.x + threadIdx.x;
    if (i == 0) d_is32 = 0;
    if (i < N_NODES) { d_deg[i] = 1; d_cursor[i] = 0; }   // self-loop in deg
    if (i < N_GRAPHS * FC_DIM) d_pooled[i] = 0.0f;
}

// Probe 4096 odd 32-bit words. int64 (values < 2^31, LE): all high words are 0.
__global__ void k_detect(const int* __restrict__ ei32) {
    int i = blockIdx.x * blockDim.x + threadIdx.x;
    if (ei32[2 * i + 1] != 0) d_is32 = 1;
}

__global__ void k_count(const void* __restrict__ ei) {
    int e = blockIdx.x * blockDim.x + threadIdx.x;
    if (e >= N_EDGES) return;
    int s, d;
    if (d_is32) {
        const int* p = (const int*)ei;
        s = p[e]; d = p[N_EDGES + e];
    } else {
        const long long* p = (const long long*)ei;
        s = (int)p[e]; d = (int)p[(size_t)N_EDGES + e];
    }
    d_edges[e] = make_int2(s, d);
    atomicAdd(&d_deg[d], 1);
}

// ---------------- 3-phase parallel exclusive scan of (deg-1) ----------------
__global__ void k_scan_part() {
    __shared__ int sh[256];
    int tid = threadIdx.x;
    int i = blockIdx.x * 256 + tid;
    int v = (i < N_NODES) ? d_deg[i] - 1 : 0;
    // warp reduce then block reduce
    for (int o = 16; o > 0; o >>= 1) v += __shfl_down_sync(0xffffffff, v, o);
    if ((tid & 31) == 0) sh[tid >> 5] = v;
    __syncthreads();
    if (tid < 8) {
        int s = sh[tid];
        for (int o = 4; o > 0; o >>= 1) s += __shfl_down_sync(0xff, s, o);
        if (tid == 0) d_bsum[blockIdx.x] = s;
    }
}

__global__ void k_scan_mid() {
    __shared__ int sh[512];
    int tid = threadIdx.x;
    int v = (tid < NBLK) ? d_bsum[tid] : 0;
    sh[tid] = v;
    __syncthreads();
    for (int off = 1; off < 512; off <<= 1) {
        int t = (tid >= off) ? sh[tid - off] : 0;
        __syncthreads();
        sh[tid] += t;
        __syncthreads();
    }
    if (tid < NBLK) d_boff[tid] = sh[tid] - v;        // exclusive
    if (tid == NBLK - 1) d_rowstart[N_NODES] = sh[tid];
}

__global__ void k_scan_write() {
    __shared__ int sh[256];
    int tid = threadIdx.x;
    int i = blockIdx.x * 256 + tid;
    int v = (i < N_NODES) ? d_deg[i] - 1 : 0;
    sh[tid] = v;
    __syncthreads();
    for (int off = 1; off < 256; off <<= 1) {
        int t = (tid >= off) ? sh[tid - off] : 0;
        __syncthreads();
        sh[tid] += t;
        __syncthreads();
    }
    if (i < N_NODES) d_rowstart[i] = sh[tid] - v + d_boff[blockIdx.x];
}

// ---------------- scatter edges into CSR (grouped by dst) -------------------
__global__ void k_scatter() {
    int e = blockIdx.x * blockDim.x + threadIdx.x;
    if (e >= N_EDGES) return;
    int2 ed = d_edges[e];
    int pos = d_rowstart[ed.y] + atomicAdd(&d_cursor[ed.y], 1);
    d_csr[pos] = ed.x;
}

// ---------------- layer-1 GEMM: g = dinv * (x @ W1)  (fp16 out) -------------
__global__ void k_gemm1(const float* __restrict__ x, const float* __restrict__ W1) {
    __shared__ float Ws[F_IN * HID];
    __shared__ float xs[4][F_IN];
    int tid = threadIdx.x;                          // 256 threads, 4 rows/block
    for (int i = tid; i < F_IN * HID; i += 256) Ws[i] = W1[i];
    int lr  = tid >> 6;
    int col = tid & 63;
    int r   = blockIdx.x * 4 + lr;                  // N divisible by 4
    if (col < F_IN) xs[lr][col] = x[(size_t)r * F_IN + col];
    __syncthreads();
    float a = 0.0f;
#pragma unroll
    for (int k = 0; k < F_IN; k++) a = fmaf(xs[lr][k], Ws[k * HID + col], a);
    float dinv = rsqrtf((float)d_deg[r]);
    d_g[(size_t)r * HID + col] = __float2half(a * dinv);
}

// ---------------- pull aggregation + fused activation -----------------------
// 16 threads/node, 8B (4 halves) each -> one 128B line per gathered row.
__global__ void k_agg(const float* __restrict__ b, int which) {
    int t = blockIdx.x * blockDim.x + threadIdx.x;
    int node = t >> 4;
    if (node >= N_NODES) return;
    int lane = t & 15;
    int c0 = lane << 2;
    const uint2* gp = (const uint2*)d_g;            // 4 halves per uint2

    uint2 w = gp[(size_t)node * 16 + lane];         // self loop
    __half2 p0 = *(__half2*)&w.x, p1 = *(__half2*)&w.y;
    float2 f0 = __half22float2(p0), f1 = __half22float2(p1);
    float ax = f0.x, ay = f0.y, az = f1.x, aw = f1.y;

    int s0 = d_rowstart[node], s1 = d_rowstart[node + 1];
    for (int i = s0; i < s1; i++) {
        int s = d_csr[i];
        uint2 u = gp[(size_t)s * 16 + lane];
        __half2 q0 = *(__half2*)&u.x, q1 = *(__half2*)&u.y;
        float2 g0 = __half22float2(q0), g1 = __half22float2(q1);
        ax += g0.x; ay += g0.y; az += g1.x; aw += g1.y;
    }
    float di = rsqrtf((float)d_deg[node]);
    float4 o;
    o.x = htanh(fmaf(di, ax, b[c0 + 0]));
    o.y = htanh(fmaf(di, ay, b[c0 + 1]));
    o.z = htanh(fmaf(di, az, b[c0 + 2]));
    o.w = htanh(fmaf(di, aw, b[c0 + 3]));
    float* dst = which ? d_h2 : d_h1;
    *(float4*)&dst[(size_t)node * HID + c0] = o;
}

// ---------------- layer-2 GEMM: g = dinv * (h1 @ W2)  (fp16 out) ------------
__global__ void k_gemm2(const float* __restrict__ W2) {
    __shared__ __align__(16) float Ws[HID * HID];
    __shared__ float xs[64][65];                     // +1 pad: conflict-free
    int tid = threadIdx.x;
    int row0 = blockIdx.x * 64;
    for (int i = tid; i < HID * HID; i += 256) Ws[i] = W2[i];
    for (int i = tid; i < 1024; i += 256) {          // 64 rows * 16 float4
        int r = i >> 4, c = (i & 15) << 2;
        int gr = row0 + r;
        float4 v = (gr < N_NODES) ? *(const float4*)&d_h1[(size_t)gr * HID + c]
                                  : make_float4(0.f, 0.f, 0.f, 0.f);
        xs[r][c] = v.x; xs[r][c + 1] = v.y; xs[r][c + 2] = v.z; xs[r][c + 3] = v.w;
    }
    __syncthreads();
    int tx = tid & 15, ty = tid >> 4;
    int c0 = tx << 2;
    float acc[4][4] = {};
#pragma unroll 8
    for (int k = 0; k < HID; k++) {
        float4 w = *(const float4*)&Ws[k * HID + c0];
#pragma unroll
        for (int r = 0; r < 4; r++) {
            float xv = xs[ty * 4 + r][k];
            acc[r][0] = fmaf(xv, w.x, acc[r][0]);
            acc[r][1] = fmaf(xv, w.y, acc[r][1]);
            acc[r][2] = fmaf(xv, w.z, acc[r][2]);
            acc[r][3] = fmaf(xv, w.w, acc[r][3]);
        }
    }
#pragma unroll
    for (int r = 0; r < 4; r++) {
        int gr = row0 + ty * 4 + r;
        if (gr < N_NODES) {
            float di = rsqrtf((float)d_deg[gr]);
            __half2 h0 = __floats2half2_rn(acc[r][0] * di, acc[r][1] * di);
            __half2 h1 = __floats2half2_rn(acc[r][2] * di, acc[r][3] * di);
            uint2 u;
            u.x = *(unsigned*)&h0; u.y = *(unsigned*)&h1;
            ((uint2*)d_g)[(size_t)gr * 16 + tx] = u;
        }
    }
}

// ---------------- graph segment boundaries (batch is sorted) ----------------
__global__ void k_bounds(const void* __restrict__ batch) {
    int g = blockIdx.x * blockDim.x + threadIdx.x;
    if (g > N_GRAPHS) return;
    const int*       b32 = (const int*)batch;
    const long long* b64 = (const long long*)batch;
    int is32 = d_is32;
    int lo = 0, hi = N_NODES;
    while (lo < hi) {
        int mid = (lo + hi) >> 1;
        long long v = is32 ? (long long)b32[mid] : b64[mid];
        if (v < (long long)g) lo = mid + 1; else hi = mid;
    }
    d_starts[g] = lo;
}

// ---------------- pooled[g] += sum over nodes of [x | h1 | h2] --------------
__global__ void k_pool(const float* __restrict__ x) {
    int g = blockIdx.x >> 3;
    int chunk = blockIdx.x & (POOL_CHUNKS - 1);
    int s = d_starts[g], e = d_starts[g + 1];
    int len = e - s;
    int cs = s + (int)(((long long)len * chunk) / POOL_CHUNKS);
    int ce = s + (int)(((long long)len * (chunk + 1)) / POOL_CHUNKS);
    int c = threadIdx.x;                             // 140 threads
    float sum = 0.0f;
    if (c < F_IN) {
        for (int i = cs; i < ce; i++) sum += x[(size_t)i * F_IN + c];
    } else if (c < F_IN + HID) {
        int cc = c - F_IN;
        for (int i = cs; i < ce; i++) sum += d_h1[(size_t)i * HID + cc];
    } else {
        int cc = c - F_IN - HID;
        for (int i = cs; i < ce; i++) sum += d_h2[(size_t)i * HID + cc];
    }
    atomicAdd(&d_pooled[g * FC_DIM + c], sum);
}

// ---------------- final FC: out = pooled @ fc_W^T + fc_b --------------------
__global__ void k_fc(const float* __restrict__ fcW, const float* __restrict__ fcb,
                     float* __restrict__ out) {
    __shared__ float ps[FC_DIM];
    int g = blockIdx.x;
    int o = threadIdx.x;                             // 140 threads
    ps[o] = d_pooled[g * FC_DIM + o];
    __syncthreads();
    float a = fcb[o];
#pragma unroll 4
    for (int k = 0; k < FC_DIM; k++) a = fmaf(ps[k], fcW[o * FC_DIM + k], a);
    out[g * FC_DIM + o] = a;
}

// ---------------- launch ----------------------------------------------------
extern "C" void kernel_launch(void* const* d_in, const int* in_sizes, int n_in,
                              void* d_out, int out_size) {
    const float* x    = (const float*)d_in[0];
    const float* W1   = (const float*)d_in[1];
    const float* b1   = (const float*)d_in[2];
    const float* W2   = (const float*)d_in[3];
    const float* b2   = (const float*)d_in[4];
    const float* fcW  = (const float*)d_in[5];
    const float* fcb  = (const float*)d_in[6];
    const void*  ei   = d_in[7];
    const void*  batch= d_in[8];
    float*       out  = (float*)d_out;

    // preprocessing: dtype probe, compact edges, degrees, CSR
    k_init      <<<(N_NODES + 255) / 256, 256>>>();
    k_detect    <<<16, 256>>>((const int*)ei);
    k_count     <<<(N_EDGES + 255) / 256, 256>>>(ei);
    k_scan_part <<<NBLK, 256>>>();
    k_scan_mid  <<<1, 512>>>();
    k_scan_write<<<NBLK, 256>>>();
    k_scatter   <<<(N_EDGES + 255) / 256, 256>>>();

    // layer 1
    k_gemm1<<<N_NODES / 4, 256>>>(x, W1);
    k_agg  <<<(N_NODES * 16 + 255) / 256, 256>>>(b1, 0);

    // layer 2
    k_gemm2<<<(N_NODES + 63) / 64, 256>>>(W2);
    k_agg  <<<(N_NODES * 16 + 255) / 256, 256>>>(b2, 1);

    // pooling + FC
    k_bounds<<<1, 512>>>(batch);
    k_pool  <<<N_GRAPHS * POOL_CHUNKS, FC_DIM>>>(x);
    k_fc    <<<N_GRAPHS, FC_DIM>>>(fcW, fcb, out);
}

// round 9
// speedup vs baseline: 2.4833x; 1.0321x over previous
#include <cuda_runtime.h>
#include <cuda_fp16.h>
#include <math.h>

#define N_NODES  100000
#define N_EDGES  1600000
#define N_GRAPHS 256
#define F_IN     12
#define HID      64
#define FC_DIM   140
#define POOL_CHUNKS 8
#define NBLK     391          // ceil(N_NODES/256)

// ---------------- scratch (device globals; no allocation in kernel_launch) ----
__device__ int   d_deg[N_NODES];
__device__ int   d_cursor[N_NODES];        // running CSR write position
__device__ int   d_rowstart[N_NODES + 1];
__device__ int   d_bsum[NBLK];
__device__ int   d_boff[NBLK];
__device__ int   d_csr[N_EDGES];
__device__ __align__(16) __half d_g [(size_t)N_NODES * HID];  // fp16 message table
__device__ __align__(16) __half d_h1[(size_t)N_NODES * HID];  // fp16 activations
__device__ __align__(16) __half d_h2[(size_t)N_NODES * HID];
__device__ float d_pooled[N_GRAPHS * FC_DIM];
__device__ int   d_starts[N_GRAPHS + 1];
__device__ int   d_is32;   // 1 if index inputs are int32, 0 if int64

__device__ __forceinline__ float htanh(float x) {
    float r;
    asm("tanh.approx.f32 %0, %1;" : "=f"(r) : "f"(x));
    return r;
}

// ---------------- init + dtype probe ----------------------------------------
__global__ void k_init() {
    int i = blockIdx.x * blockDim.x + threadIdx.x;
    if (i == 0) d_is32 = 0;
    if (i < N_NODES) d_deg[i] = 1;                 // self-loop in deg
    if (i < N_GRAPHS * FC_DIM) d_pooled[i] = 0.0f;
}

// Probe 4096 odd 32-bit words. int64 (values < 2^31, LE): all high words are 0.
__global__ void k_detect(const int* __restrict__ ei32) {
    int i = blockIdx.x * blockDim.x + threadIdx.x;
    if (ei32[2 * i + 1] != 0) d_is32 = 1;
}

// count only needs dst (second half of edge_index)
__global__ void k_count(const void* __restrict__ ei) {
    int e = blockIdx.x * blockDim.x + threadIdx.x;
    if (e >= N_EDGES) return;
    int d;
    if (d_is32) d = ((const int*)ei)[N_EDGES + e];
    else        d = (int)((const long long*)ei)[(size_t)N_EDGES + e];
    atomicAdd(&d_deg[d], 1);
}

// ---------------- 3-phase parallel exclusive scan of (deg-1) ----------------
__global__ void k_scan_part() {
    __shared__ int sh[8];
    int tid = threadIdx.x;
    int i = blockIdx.x * 256 + tid;
    int v = (i < N_NODES) ? d_deg[i] - 1 : 0;
    for (int o = 16; o > 0; o >>= 1) v += __shfl_down_sync(0xffffffff, v, o);
    if ((tid & 31) == 0) sh[tid >> 5] = v;
    __syncthreads();
    if (tid < 8) {
        int s = sh[tid];
        for (int o = 4; o > 0; o >>= 1) s += __shfl_down_sync(0xff, s, o);
        if (tid == 0) d_bsum[blockIdx.x] = s;
    }
}

__global__ void k_scan_mid() {
    __shared__ int sh[512];
    int tid = threadIdx.x;
    int v = (tid < NBLK) ? d_bsum[tid] : 0;
    sh[tid] = v;
    __syncthreads();
    for (int off = 1; off < 512; off <<= 1) {
        int t = (tid >= off) ? sh[tid - off] : 0;
        __syncthreads();
        sh[tid] += t;
        __syncthreads();
    }
    if (tid < NBLK) d_boff[tid] = sh[tid] - v;        // exclusive
    if (tid == NBLK - 1) d_rowstart[N_NODES] = sh[tid];
}

__global__ void k_scan_write() {
    __shared__ int sh[256];
    int tid = threadIdx.x;
    int i = blockIdx.x * 256 + tid;
    int v = (i < N_NODES) ? d_deg[i] - 1 : 0;
    sh[tid] = v;
    __syncthreads();
    for (int off = 1; off < 256; off <<= 1) {
        int t = (tid >= off) ? sh[tid - off] : 0;
        __syncthreads();
        sh[tid] += t;
        __syncthreads();
    }
    if (i < N_NODES) {
        int rs = sh[tid] - v + d_boff[blockIdx.x];
        d_rowstart[i] = rs;
        d_cursor[i]   = rs;                           // scatter cursor starts here
    }
}

// ---------------- scatter edges into CSR (grouped by dst) -------------------
__global__ void k_scatter(const void* __restrict__ ei) {
    int e = blockIdx.x * blockDim.x + threadIdx.x;
    if (e >= N_EDGES) return;
    int s, d;
    if (d_is32) {
        const int* p = (const int*)ei;
        s = p[e]; d = p[N_EDGES + e];
    } else {
        const long long* p = (const long long*)ei;
        s = (int)p[e]; d = (int)p[(size_t)N_EDGES + e];
    }
    int pos = atomicAdd(&d_cursor[d], 1);
    d_csr[pos] = s;
}

// ---------------- layer-1 GEMM: g = dinv * (x @ W1)  (fp16 out) -------------
__global__ void k_gemm1(const float* __restrict__ x, const float* __restrict__ W1) {
    __shared__ float Ws[F_IN * HID];
    __shared__ float xs[4][F_IN];
    int tid = threadIdx.x;                          // 256 threads, 4 rows/block
    for (int i = tid; i < F_IN * HID; i += 256) Ws[i] = W1[i];
    int lr  = tid >> 6;
    int col = tid & 63;
    int r   = blockIdx.x * 4 + lr;                  // N divisible by 4
    if (col < F_IN) xs[lr][col] = x[(size_t)r * F_IN + col];
    __syncthreads();
    float a = 0.0f;
#pragma unroll
    for (int k = 0; k < F_IN; k++) a = fmaf(xs[lr][k], Ws[k * HID + col], a);
    float dinv = rsqrtf((float)d_deg[r]);
    d_g[(size_t)r * HID + col] = __float2half(a * dinv);
}

// ---------------- pull aggregation + fused activation (fp16 h out) ----------
// 16 threads/node, 8B (4 halves) each -> one 128B line per gathered row.
__global__ void k_agg(const float* __restrict__ b, int which) {
    int t = blockIdx.x * blockDim.x + threadIdx.x;
    int node = t >> 4;
    if (node >= N_NODES) return;
    int lane = t & 15;
    int c0 = lane << 2;
    const uint2* gp = (const uint2*)d_g;            // 4 halves per uint2

    uint2 w = gp[(size_t)node * 16 + lane];         // self loop
    __half2 p0 = *(__half2*)&w.x, p1 = *(__half2*)&w.y;
    float2 f0 = __half22float2(p0), f1 = __half22float2(p1);
    float ax = f0.x, ay = f0.y, az = f1.x, aw = f1.y;
    float bx = 0.f, by = 0.f, bz = 0.f, bw = 0.f;   // second accumulator (MLP)

    int s0 = d_rowstart[node], s1 = d_rowstart[node + 1];
    int i = s0;
    for (; i + 1 < s1; i += 2) {
        int sA = d_csr[i], sB = d_csr[i + 1];
        uint2 uA = gp[(size_t)sA * 16 + lane];
        uint2 uB = gp[(size_t)sB * 16 + lane];
        float2 a0 = __half22float2(*(__half2*)&uA.x), a1 = __half22float2(*(__half2*)&uA.y);
        float2 b0 = __half22float2(*(__half2*)&uB.x), b1 = __half22float2(*(__half2*)&uB.y);
        ax += a0.x; ay += a0.y; az += a1.x; aw += a1.y;
        bx += b0.x; by += b0.y; bz += b1.x; bw += b1.y;
    }
    if (i < s1) {
        int s = d_csr[i];
        uint2 u = gp[(size_t)s * 16 + lane];
        float2 g0 = __half22float2(*(__half2*)&u.x), g1 = __half22float2(*(__half2*)&u.y);
        ax += g0.x; ay += g0.y; az += g1.x; aw += g1.y;
    }
    ax += bx; ay += by; az += bz; aw += bw;

    float di = rsqrtf((float)d_deg[node]);
    float ox = htanh(fmaf(di, ax, b[c0 + 0]));
    float oy = htanh(fmaf(di, ay, b[c0 + 1]));
    float oz = htanh(fmaf(di, az, b[c0 + 2]));
    float ow = htanh(fmaf(di, aw, b[c0 + 3]));
    __half2 h0 = __floats2half2_rn(ox, oy);
    __half2 h1 = __floats2half2_rn(oz, ow);
    uint2 u;
    u.x = *(unsigned*)&h0; u.y = *(unsigned*)&h1;
    uint2* dst = (uint2*)(which ? d_h2 : d_h1);
    dst[(size_t)node * 16 + lane] = u;
}

// ---------------- layer-2 GEMM: g = dinv * (h1 @ W2)  (fp16 in/out) ---------
__global__ void k_gemm2(const float* __restrict__ W2) {
    __shared__ __align__(16) float Ws[HID * HID];
    __shared__ float xs[64][65];                     // +1 pad: conflict-free
    int tid = threadIdx.x;
    int row0 = blockIdx.x * 64;
    for (int i = tid; i < HID * HID; i += 256) Ws[i] = W2[i];
    const uint2* hp = (const uint2*)d_h1;
    for (int i = tid; i < 1024; i += 256) {          // 64 rows * 16 uint2
        int r = i >> 4, c4 = i & 15;
        int gr = row0 + r;
        float2 g0, g1;
        if (gr < N_NODES) {
            uint2 u = hp[(size_t)gr * 16 + c4];
            g0 = __half22float2(*(__half2*)&u.x);
            g1 = __half22float2(*(__half2*)&u.y);
        } else { g0 = make_float2(0.f, 0.f); g1 = make_float2(0.f, 0.f); }
        int c = c4 << 2;
        xs[r][c] = g0.x; xs[r][c + 1] = g0.y; xs[r][c + 2] = g1.x; xs[r][c + 3] = g1.y;
    }
    __syncthreads();
    int tx = tid & 15, ty = tid >> 4;
    int c0 = tx << 2;
    float acc[4][4] = {};
#pragma unroll 8
    for (int k = 0; k < HID; k++) {
        float4 w = *(const float4*)&Ws[k * HID + c0];
#pragma unroll
        for (int r = 0; r < 4; r++) {
            float xv = xs[ty * 4 + r][k];
            acc[r][0] = fmaf(xv, w.x, acc[r][0]);
            acc[r][1] = fmaf(xv, w.y, acc[r][1]);
            acc[r][2] = fmaf(xv, w.z, acc[r][2]);
            acc[r][3] = fmaf(xv, w.w, acc[r][3]);
        }
    }
#pragma unroll
    for (int r = 0; r < 4; r++) {
        int gr = row0 + ty * 4 + r;
        if (gr < N_NODES) {
            float di = rsqrtf((float)d_deg[gr]);
            __half2 h0 = __floats2half2_rn(acc[r][0] * di, acc[r][1] * di);
            __half2 h1 = __floats2half2_rn(acc[r][2] * di, acc[r][3] * di);
            uint2 u;
            u.x = *(unsigned*)&h0; u.y = *(unsigned*)&h1;
            ((uint2*)d_g)[(size_t)gr * 16 + tx] = u;
        }
    }
}

// ---------------- graph segment boundaries (batch is sorted) ----------------
__global__ void k_bounds(const void* __restrict__ batch) {
    int g = blockIdx.x * blockDim.x + threadIdx.x;
    if (g > N_GRAPHS) return;
    const int*       b32 = (const int*)batch;
    const long long* b64 = (const long long*)batch;
    int is32 = d_is32;
    int lo = 0, hi = N_NODES;
    while (lo < hi) {
        int mid = (lo + hi) >> 1;
        long long v = is32 ? (long long)b32[mid] : b64[mid];
        if (v < (long long)g) lo = mid + 1; else hi = mid;
    }
    d_starts[g] = lo;
}

// ---------------- pooled[g] += sum over nodes of [x | h1 | h2] --------------
__global__ void k_pool(const float* __restrict__ x) {
    int g = blockIdx.x >> 3;
    int chunk = blockIdx.x & (POOL_CHUNKS - 1);
    int s = d_starts[g], e = d_starts[g + 1];
    int len = e - s;
    int cs = s + (int)(((long long)len * chunk) / POOL_CHUNKS);
    int ce = s + (int)(((long long)len * (chunk + 1)) / POOL_CHUNKS);
    int c = threadIdx.x;                             // 140 threads
    float sum = 0.0f;
    if (c < F_IN) {
        for (int i = cs; i < ce; i++) sum += x[(size_t)i * F_IN + c];
    } else if (c < F_IN + HID) {
        int cc = c - F_IN;
        for (int i = cs; i < ce; i++) sum += __half2float(d_h1[(size_t)i * HID + cc]);
    } else {
        int cc = c - F_IN - HID;
        for (int i = cs; i < ce; i++) sum += __half2float(d_h2[(size_t)i * HID + cc]);
    }
    atomicAdd(&d_pooled[g * FC_DIM + c], sum);
}

// ---------------- final FC: out = pooled @ fc_W^T + fc_b --------------------
__global__ void k_fc(const float* __restrict__ fcW, const float* __restrict__ fcb,
                     float* __restrict__ out) {
    __shared__ float ps[FC_DIM];
    int g = blockIdx.x;
    int o = threadIdx.x;                             // 140 threads
    ps[o] = d_pooled[g * FC_DIM + o];
    __syncthreads();
    float a = fcb[o];
#pragma unroll 4
    for (int k = 0; k < FC_DIM; k++) a = fmaf(ps[k], fcW[o * FC_DIM + k], a);
    out[g * FC_DIM + o] = a;
}

// ---------------- launch ----------------------------------------------------
extern "C" void kernel_launch(void* const* d_in, const int* in_sizes, int n_in,
                              void* d_out, int out_size) {
    const float* x    = (const float*)d_in[0];
    const float* W1   = (const float*)d_in[1];
    const float* b1   = (const float*)d_in[2];
    const float* W2   = (const float*)d_in[3];
    const float* b2   = (const float*)d_in[4];
    const float* fcW  = (const float*)d_in[5];
    const float* fcb  = (const float*)d_in[6];
    const void*  ei   = d_in[7];
    const void*  batch= d_in[8];
    float*       out  = (float*)d_out;

    // preprocessing: dtype probe, degrees, CSR
    k_init      <<<(N_NODES + 255) / 256, 256>>>();
    k_detect    <<<16, 256>>>((const int*)ei);
    k_count     <<<(N_EDGES + 255) / 256, 256>>>(ei);
    k_scan_part <<<NBLK, 256>>>();
    k_scan_mid  <<<1, 512>>>();
    k_scan_write<<<NBLK, 256>>>();
    k_scatter   <<<(N_EDGES + 255) / 256, 256>>>(ei);

    // layer 1
    k_gemm1<<<N_NODES / 4, 256>>>(x, W1);
    k_agg  <<<(N_NODES * 16 + 255) / 256, 256>>>(b1, 0);

    // layer 2
    k_gemm2<<<(N_NODES + 63) / 64, 256>>>(W2);
    k_agg  <<<(N_NODES * 16 + 255) / 256, 256>>>(b2, 1);

    // pooling + FC
    k_bounds<<<1, 512>>>(batch);
    k_pool  <<<N_GRAPHS * POOL_CHUNKS, FC_DIM>>>(x);
    k_fc    <<<N_GRAPHS, FC_DIM>>>(fcW, fcb, out);
}

// round 13
// speedup vs baseline: 2.6812x; 1.0797x over previous
#include <cuda_runtime.h>
#include <cuda_fp16.h>
#include <math.h>

#define N_NODES  100000
#define N_EDGES  1600000
#define N_GRAPHS 256
#define F_IN     12
#define HID      64
#define FC_DIM   140
#define POOL_CHUNKS 8
#define NBLK     391          // ceil(N_NODES/256)

// ---------------- scratch (device globals; no allocation in kernel_launch) ----
__device__ int   d_deg[N_NODES];
__device__ int   d_cursor[N_NODES];        // running CSR write position
__device__ int   d_rowstart[N_NODES + 1];
__device__ int   d_bsum[NBLK];
__device__ int   d_csr[N_EDGES];
__device__ __align__(16) __half d_g [(size_t)N_NODES * HID];  // fp16 message table
__device__ __align__(16) __half d_h1[(size_t)N_NODES * HID];  // fp16 activations
__device__ __align__(16) __half d_h2[(size_t)N_NODES * HID];
__device__ float d_pooled[N_GRAPHS * FC_DIM];
__device__ int   d_starts[N_GRAPHS + 1];
__device__ int   d_is32 = 0;   // set-once monotone flag: 1 if indices are int32

__device__ __forceinline__ float htanh(float x) {
    float r;
    asm("tanh.approx.f32 %0, %1;" : "=f"(r) : "f"(x));
    return r;
}

// ---------------- fused init + dtype probe ----------------------------------
// d_is32 is statically 0 and only ever set to 1 (same input every call ->
// deterministic across graph replays).
__global__ void k_init(const int* __restrict__ ei32) {
    int i = blockIdx.x * blockDim.x + threadIdx.x;
    if (i < N_NODES) d_deg[i] = 1;                 // self-loop in deg
    if (i < N_GRAPHS * FC_DIM) d_pooled[i] = 0.0f;
    // int64 (values < 2^31, LE): every odd 32-bit word is 0. int32: random ids.
    if (i < 4096 && ei32[2 * i + 1] != 0) d_is32 = 1;
}

// count only needs dst (second half of edge_index)
__global__ void k_count(const void* __restrict__ ei) {
    int e = blockIdx.x * blockDim.x + threadIdx.x;
    if (e >= N_EDGES) return;
    int d;
    if (d_is32) d = ((const int*)ei)[N_EDGES + e];
    else        d = (int)((const long long*)ei)[(size_t)N_EDGES + e];
    atomicAdd(&d_deg[d], 1);
}

// ---------------- scan phase 1: per-block sums (+ folded k_bounds) ----------
__global__ void k_scan_part(const void* __restrict__ batch) {
    int bid = blockIdx.x;
    if (bid >= NBLK) {                               // folded segment bounds
        int g = (bid - NBLK) * 256 + threadIdx.x;
        if (g > N_GRAPHS) return;
        const int*       b32 = (const int*)batch;
        const long long* b64 = (const long long*)batch;
        int is32 = d_is32;
        int lo = 0, hi = N_NODES;
        while (lo < hi) {
            int mid = (lo + hi) >> 1;
            long long v = is32 ? (long long)b32[mid] : b64[mid];
            if (v < (long long)g) lo = mid + 1; else hi = mid;
        }
        d_starts[g] = lo;
        return;
    }
    __shared__ int sh[8];
    int tid = threadIdx.x;
    int i = bid * 256 + tid;
    int v = (i < N_NODES) ? d_deg[i] - 1 : 0;
    for (int o = 16; o > 0; o >>= 1) v += __shfl_down_sync(0xffffffff, v, o);
    if ((tid & 31) == 0) sh[tid >> 5] = v;
    __syncthreads();
    if (tid < 8) {
        int s = sh[tid];
        for (int o = 4; o > 0; o >>= 1) s += __shfl_down_sync(0xff, s, o);
        if (tid == 0) d_bsum[bid] = s;
    }
}

// ---------------- scan phase 2: offset reduce + local scan + write ----------
__global__ void k_scan_write() {
    __shared__ int sh[256];
    __shared__ int ws[8];
    int tid = threadIdx.x, bid = blockIdx.x;
    // offset = sum of d_bsum[0..bid-1] (<=391 ints, L2-hot)
    int part = 0;
    for (int j = tid; j < bid; j += 256) part += d_bsum[j];
    for (int o = 16; o > 0; o >>= 1) part += __shfl_down_sync(0xffffffff, part, o);
    if ((tid & 31) == 0) ws[tid >> 5] = part;
    __syncthreads();
    if (tid < 8) {
        int s = ws[tid];
        for (int o = 4; o > 0; o >>= 1) s += __shfl_down_sync(0xff, s, o);
        if (tid == 0) ws[0] = s;
    }
    __syncthreads();
    int offset = ws[0];
    // local inclusive scan of deg-1
    int i = bid * 256 + tid;
    int v = (i < N_NODES) ? d_deg[i] - 1 : 0;
    sh[tid] = v;
    __syncthreads();
    for (int off = 1; off < 256; off <<= 1) {
        int t = (tid >= off) ? sh[tid - off] : 0;
        __syncthreads();
        sh[tid] += t;
        __syncthreads();
    }
    if (i < N_NODES) {
        int rs = sh[tid] - v + offset;
        d_rowstart[i] = rs;
        d_cursor[i]   = rs;                           // scatter cursor starts here
    }
    if (bid == NBLK - 1 && tid == 255) d_rowstart[N_NODES] = offset + sh[255];
}

// ---------------- scatter edges into CSR (grouped by dst) -------------------
__global__ void k_scatter(const void* __restrict__ ei) {
    int e = blockIdx.x * blockDim.x + threadIdx.x;
    if (e >= N_EDGES) return;
    int s, d;
    if (d_is32) {
        const int* p = (const int*)ei;
        s = p[e]; d = p[N_EDGES + e];
    } else {
        const long long* p = (const long long*)ei;
        s = (int)p[e]; d = (int)p[(size_t)N_EDGES + e];
    }
    int pos = atomicAdd(&d_cursor[d], 1);
    d_csr[pos] = s;
}

// ---------------- layer-1 GEMM: g = dinv * (x @ W1)  (fp16 out) -------------
__global__ void k_gemm1(const float* __restrict__ x, const float* __restrict__ W1) {
    __shared__ float Ws[F_IN * HID];
    __shared__ float xs[4][F_IN];
    int tid = threadIdx.x;                          // 256 threads, 4 rows/block
    for (int i = tid; i < F_IN * HID; i += 256) Ws[i] = W1[i];
    int lr  = tid >> 6;
    int col = tid & 63;
    int r   = blockIdx.x * 4 + lr;                  // N divisible by 4
    if (col < F_IN) xs[lr][col] = x[(size_t)r * F_IN + col];
    __syncthreads();
    float a = 0.0f;
#pragma unroll
    for (int k = 0; k < F_IN; k++) a = fmaf(xs[lr][k], Ws[k * HID + col], a);
    float dinv = rsqrtf((float)d_deg[r]);
    d_g[(size_t)r * HID + col] = __float2half(a * dinv);
}

// ---------------- pull aggregation + fused activation (fp16 h out) ----------
// 8 threads/node, 16B (8 halves) each -> one 128B line per gathered row,
// half the load instructions of the uint2 version.
__global__ void k_agg(const float* __restrict__ bias, int which) {
    int t = blockIdx.x * blockDim.x + threadIdx.x;
    int node = t >> 3;
    if (node >= N_NODES) return;
    int lane = t & 7;
    int c0 = lane << 3;
    const uint4* gp = (const uint4*)d_g;            // 8 halves per uint4

    float a[8], b2[8];
    {
        uint4 w = gp[(size_t)node * 8 + lane];      // self loop
        float2 f0 = __half22float2(*(__half2*)&w.x);
        float2 f1 = __half22float2(*(__half2*)&w.y);
        float2 f2 = __half22float2(*(__half2*)&w.z);
        float2 f3 = __half22float2(*(__half2*)&w.w);
        a[0]=f0.x; a[1]=f0.y; a[2]=f1.x; a[3]=f1.y;
        a[4]=f2.x; a[5]=f2.y; a[6]=f3.x; a[7]=f3.y;
    }
#pragma unroll
    for (int k = 0; k < 8; k++) b2[k] = 0.0f;

    int s0 = d_rowstart[node], s1 = d_rowstart[node + 1];
    int i = s0;
    for (; i + 1 < s1; i += 2) {
        int sA = d_csr[i], sB = d_csr[i + 1];
        uint4 uA = gp[(size_t)sA * 8 + lane];
        uint4 uB = gp[(size_t)sB * 8 + lane];
        float2 x0 = __half22float2(*(__half2*)&uA.x), x1 = __half22float2(*(__half2*)&uA.y);
        float2 x2 = __half22float2(*(__half2*)&uA.z), x3 = __half22float2(*(__half2*)&uA.w);
        float2 y0 = __half22float2(*(__half2*)&uB.x), y1 = __half22float2(*(__half2*)&uB.y);
        float2 y2 = __half22float2(*(__half2*)&uB.z), y3 = __half22float2(*(__half2*)&uB.w);
        a[0]+=x0.x; a[1]+=x0.y; a[2]+=x1.x; a[3]+=x1.y;
        a[4]+=x2.x; a[5]+=x2.y; a[6]+=x3.x; a[7]+=x3.y;
        b2[0]+=y0.x; b2[1]+=y0.y; b2[2]+=y1.x; b2[3]+=y1.y;
        b2[4]+=y2.x; b2[5]+=y2.y; b2[6]+=y3.x; b2[7]+=y3.y;
    }
    if (i < s1) {
        int s = d_csr[i];
        uint4 u = gp[(size_t)s * 8 + lane];
        float2 x0 = __half22float2(*(__half2*)&u.x), x1 = __half22float2(*(__half2*)&u.y);
        float2 x2 = __half22float2(*(__half2*)&u.z), x3 = __half22float2(*(__half2*)&u.w);
        a[0]+=x0.x; a[1]+=x0.y; a[2]+=x1.x; a[3]+=x1.y;
        a[4]+=x2.x; a[5]+=x2.y; a[6]+=x3.x; a[7]+=x3.y;
    }
#pragma unroll
    for (int k = 0; k < 8; k++) a[k] += b2[k];

    float di = rsqrtf((float)d_deg[node]);
    float o[8];
#pragma unroll
    for (int k = 0; k < 8; k++) o[k] = htanh(fmaf(di, a[k], bias[c0 + k]));
    __half2 h0 = __floats2half2_rn(o[0], o[1]);
    __half2 h1 = __floats2half2_rn(o[2], o[3]);
    __half2 h2 = __floats2half2_rn(o[4], o[5]);
    __half2 h3 = __floats2half2_rn(o[6], o[7]);
    uint4 u;
    u.x = *(unsigned*)&h0; u.y = *(unsigned*)&h1;
    u.z = *(unsigned*)&h2; u.w = *(unsigned*)&h3;
    uint4* dst = (uint4*)(which ? d_h2 : d_h1);
    dst[(size_t)node * 8 + lane] = u;
}

// ---------------- layer-2 GEMM: g = dinv * (h1 @ W2)  (fp16 in/out) ---------
__global__ void k_gemm2(const float* __restrict__ W2) {
    __shared__ __align__(16) float Ws[HID * HID];
    __shared__ float xs[64][65];                     // +1 pad: conflict-free
    int tid = threadIdx.x;
    int row0 = blockIdx.x * 64;
    for (int i = tid; i < HID * HID; i += 256) Ws[i] = W2[i];
    const uint4* hp = (const uint4*)d_h1;
    for (int i = tid; i < 512; i += 256) {           // 64 rows * 8 uint4
        int r = i >> 3, c8 = i & 7;
        int gr = row0 + r;
        float2 g0, g1, g2, g3;
        if (gr < N_NODES) {
            uint4 u = hp[(size_t)gr * 8 + c8];
            g0 = __half22float2(*(__half2*)&u.x);
            g1 = __half22float2(*(__half2*)&u.y);
            g2 = __half22float2(*(__half2*)&u.z);
            g3 = __half22float2(*(__half2*)&u.w);
        } else {
            g0 = g1 = g2 = g3 = make_float2(0.f, 0.f);
        }
        int c = c8 << 3;
        xs[r][c]     = g0.x; xs[r][c + 1] = g0.y;
        xs[r][c + 2] = g1.x; xs[r][c + 3] = g1.y;
        xs[r][c + 4] = g2.x; xs[r][c + 5] = g2.y;
        xs[r][c + 6] = g3.x; xs[r][c + 7] = g3.y;
    }
    __syncthreads();
    int tx = tid & 15, ty = tid >> 4;
    int c0 = tx << 2;
    float acc[4][4] = {};
#pragma unroll 8
    for (int k = 0; k < HID; k++) {
        float4 w = *(const float4*)&Ws[k * HID + c0];
#pragma unroll
        for (int r = 0; r < 4; r++) {
            float xv = xs[ty * 4 + r][k];
            acc[r][0] = fmaf(xv, w.x, acc[r][0]);
            acc[r][1] = fmaf(xv, w.y, acc[r][1]);
            acc[r][2] = fmaf(xv, w.z, acc[r][2]);
            acc[r][3] = fmaf(xv, w.w, acc[r][3]);
        }
    }
#pragma unroll
    for (int r = 0; r < 4; r++) {
        int gr = row0 + ty * 4 + r;
        if (gr < N_NODES) {
            float di = rsqrtf((float)d_deg[gr]);
            __half2 h0 = __floats2half2_rn(acc[r][0] * di, acc[r][1] * di);
            __half2 h1 = __floats2half2_rn(acc[r][2] * di, acc[r][3] * di);
            uint2 u;
            u.x = *(unsigned*)&h0; u.y = *(unsigned*)&h1;
            ((uint2*)d_g)[(size_t)gr * 16 + tx] = u;
        }
    }
}

// ---------------- pooled[g] += sum over nodes of [x | h1 | h2] --------------
__global__ void k_pool(const float* __restrict__ x) {
    int g = blockIdx.x >> 3;
    int chunk = blockIdx.x & (POOL_CHUNKS - 1);
    int s = d_starts[g], e = d_starts[g + 1];
    int len = e - s;
    int cs = s + (int)(((long long)len * chunk) / POOL_CHUNKS);
    int ce = s + (int)(((long long)len * (chunk + 1)) / POOL_CHUNKS);
    int c = threadIdx.x;                             // 140 threads
    float sum = 0.0f;
    if (c < F_IN) {
        for (int i = cs; i < ce; i++) sum += x[(size_t)i * F_IN + c];
    } else if (c < F_IN + HID) {
        int cc = c - F_IN;
        for (int i = cs; i < ce; i++) sum += __half2float(d_h1[(size_t)i * HID + cc]);
    } else {
        int cc = c - F_IN - HID;
        for (int i = cs; i < ce; i++) sum += __half2float(d_h2[(size_t)i * HID + cc]);
    }
    atomicAdd(&d_pooled[g * FC_DIM + c], sum);
}

// ---------------- final FC: out = pooled @ fc_W^T + fc_b --------------------
__global__ void k_fc(const float* __restrict__ fcW, const float* __restrict__ fcb,
                     float* __restrict__ out) {
    __shared__ float ps[FC_DIM];
    int g = blockIdx.x;
    int o = threadIdx.x;                             // 140 threads
    ps[o] = d_pooled[g * FC_DIM + o];
    __syncthreads();
    float a = fcb[o];
#pragma unroll 4
    for (int k = 0; k < FC_DIM; k++) a = fmaf(ps[k], fcW[o * FC_DIM + k], a);
    out[g * FC_DIM + o] = a;
}

// ---------------- launch ----------------------------------------------------
extern "C" void kernel_launch(void* const* d_in, const int* in_sizes, int n_in,
                              void* d_out, int out_size) {
    const float* x    = (const float*)d_in[0];
    const float* W1   = (const float*)d_in[1];
    const float* b1   = (const float*)d_in[2];
    const float* W2   = (const float*)d_in[3];
    const float* b2   = (const float*)d_in[4];
    const float* fcW  = (const float*)d_in[5];
    const float* fcb  = (const float*)d_in[6];
    const void*  ei   = d_in[7];
    const void*  batch= d_in[8];
    float*       out  = (float*)d_out;

    // preprocessing: init+probe, degrees, scan(+bounds), CSR
    k_init      <<<(N_NODES + 255) / 256, 256>>>((const int*)ei);
    k_count     <<<(N_EDGES + 255) / 256, 256>>>(ei);
    k_scan_part <<<NBLK + 2, 256>>>(batch);
    k_scan_write<<<NBLK, 256>>>();
    k_scatter   <<<(N_EDGES + 255) / 256, 256>>>(ei);

    // layer 1
    k_gemm1<<<N_NODES / 4, 256>>>(x, W1);
    k_agg  <<<(N_NODES * 8 + 255) / 256, 256>>>(b1, 0);

    // layer 2
    k_gemm2<<<(N_NODES + 63) / 64, 256>>>(W2);
    k_agg  <<<(N_NODES * 8 + 255) / 256, 256>>>(b2, 1);

    // pooling + FC
    k_pool<<<N_GRAPHS * POOL_CHUNKS, FC_DIM>>>(x);
    k_fc  <<<N_GRAPHS, FC_DIM>>>(fcW, fcb, out);
}